// round 3
// baseline (speedup 1.0000x reference)
#include <cuda_runtime.h>
#include <math.h>

// Problem constants
#define BATCH 4
#define SEQ   2048
#define DIMC  1024
#define NH    16
#define HD    64
#define HID   2048
#define MTOK  (BATCH * SEQ)   // 8192 tokens

// ---------------------------------------------------------------------------
// Scratch buffers (static __device__ globals; no allocations allowed)
// ---------------------------------------------------------------------------
__device__ float g_qkv[(size_t)MTOK * 3 * DIMC];   // 96 MB  [b,n,(3,h,d)]
__device__ float g_attn[(size_t)MTOK * DIMC];      // 32 MB  [b,n,h*d]
__device__ float g_proj[(size_t)MTOK * DIMC];      // 32 MB
__device__ float g_x1[(size_t)MTOK * HID];         // 64 MB
__device__ float g_x2[(size_t)MTOK * HID];         // 64 MB

// ---------------------------------------------------------------------------
// Packed fp32x2 helpers (sm_103a: doubles fp32 FMA throughput vs scalar FFMA)
// ---------------------------------------------------------------------------
__device__ __forceinline__ unsigned long long ffma2(unsigned long long a,
                                                    unsigned long long b,
                                                    unsigned long long c) {
    unsigned long long d;
    asm("fma.rn.f32x2 %0, %1, %2, %3;" : "=l"(d) : "l"(a), "l"(b), "l"(c));
    return d;
}
__device__ __forceinline__ unsigned long long dup2(float a) {
    unsigned long long d;
    asm("mov.b64 %0, {%1, %1};" : "=l"(d) : "f"(a));
    return d;
}
__device__ __forceinline__ float2 unpk2(unsigned long long v) {
    float lo, hi;
    asm("mov.b64 {%0, %1}, %2;" : "=f"(lo), "=f"(hi) : "l"(v));
    return make_float2(lo, hi);
}

// ---------------------------------------------------------------------------
// Generic NT GEMM:  C[M,N] = A[M,K] @ W[N,K]^T (+ bias[N])
// BM=64, BN=128, BK=16, 256 threads, per-thread 4 rows x 8 cols (f32x2 packed)
// Requires M%64==0, N%128==0, K%16==0 (true for all shapes here).
// ---------------------------------------------------------------------------
#define GBM 64
#define GBN 128
#define GBK 16

__global__ __launch_bounds__(256) void gemm_nt_kernel(
    const float* __restrict__ A, const float* __restrict__ W,
    const float* __restrict__ bias, float* __restrict__ C,
    int M, int N, int K)
{
    __shared__ float As[GBK * GBM];   // [k][m]
    __shared__ float Bs[GBK * GBN];   // [k][n]

    const int tid = threadIdx.x;
    const int tx = tid & 15;          // n-direction (8 cols each)
    const int ty = tid >> 4;          // m-direction (4 rows each)
    const int m0 = blockIdx.y * GBM;
    const int n0 = blockIdx.x * GBN;

    unsigned long long acc[4][4];
#pragma unroll
    for (int i = 0; i < 4; i++)
#pragma unroll
        for (int j = 0; j < 4; j++) acc[i][j] = 0ull;

    const int lrow = tid >> 2;          // 0..63
    const int lkc  = (tid & 3) * 4;     // 0,4,8,12
    const float* aptr  = A + (size_t)(m0 + lrow) * K + lkc;
    const float* bptr0 = W + (size_t)(n0 + lrow) * K + lkc;
    const float* bptr1 = W + (size_t)(n0 + lrow + 64) * K + lkc;

    for (int k0 = 0; k0 < K; k0 += GBK) {
        const float4 av  = *(const float4*)(aptr + k0);
        const float4 bv0 = *(const float4*)(bptr0 + k0);
        const float4 bv1 = *(const float4*)(bptr1 + k0);
        __syncthreads();   // previous iter's smem reads done before overwrite
        As[(lkc + 0) * GBM + lrow] = av.x;
        As[(lkc + 1) * GBM + lrow] = av.y;
        As[(lkc + 2) * GBM + lrow] = av.z;
        As[(lkc + 3) * GBM + lrow] = av.w;
        Bs[(lkc + 0) * GBN + lrow] = bv0.x;
        Bs[(lkc + 1) * GBN + lrow] = bv0.y;
        Bs[(lkc + 2) * GBN + lrow] = bv0.z;
        Bs[(lkc + 3) * GBN + lrow] = bv0.w;
        Bs[(lkc + 0) * GBN + lrow + 64] = bv1.x;
        Bs[(lkc + 1) * GBN + lrow + 64] = bv1.y;
        Bs[(lkc + 2) * GBN + lrow + 64] = bv1.z;
        Bs[(lkc + 3) * GBN + lrow + 64] = bv1.w;
        __syncthreads();

#pragma unroll
        for (int k = 0; k < GBK; k++) {
            const float4 a4 = *(const float4*)&As[k * GBM + ty * 4];
            const ulonglong2 bq0 = *(const ulonglong2*)&Bs[k * GBN + tx * 8];
            const ulonglong2 bq1 = *(const ulonglong2*)&Bs[k * GBN + tx * 8 + 4];
            unsigned long long ad[4] = {dup2(a4.x), dup2(a4.y), dup2(a4.z), dup2(a4.w)};
            unsigned long long bb[4] = {bq0.x, bq0.y, bq1.x, bq1.y};
#pragma unroll
            for (int i = 0; i < 4; i++) {
#pragma unroll
                for (int j = 0; j < 4; j++) {
                    acc[i][j] = ffma2(ad[i], bb[j], acc[i][j]);
                }
            }
        }
    }

    // Epilogue: unpack, add bias, store
#pragma unroll
    for (int i = 0; i < 4; i++) {
        const int m = m0 + ty * 4 + i;
        const int n = n0 + tx * 8;
        float o[8];
#pragma unroll
        for (int j = 0; j < 4; j++) {
            float2 v = unpk2(acc[i][j]);
            o[2 * j]     = v.x;
            o[2 * j + 1] = v.y;
        }
        if (bias != nullptr) {
#pragma unroll
            for (int jj = 0; jj < 8; jj++) o[jj] += bias[n + jj];
        }
        float4 r0 = make_float4(o[0], o[1], o[2], o[3]);
        float4 r1 = make_float4(o[4], o[5], o[6], o[7]);
        *(float4*)&C[(size_t)m * N + n]     = r0;
        *(float4*)&C[(size_t)m * N + n + 4] = r1;
    }
}

// ---------------------------------------------------------------------------
// RoPE applied in-place on Q and K slices of g_qkv.
// idx = ((((b*SEQ + n)*2 + s)*NH + h)*32 + j), total 2^23 threads.
// ---------------------------------------------------------------------------
__global__ void rope_kernel(float* __restrict__ qkv)
{
    const int idx = blockIdx.x * blockDim.x + threadIdx.x;
    const int j = idx & 31;
    const int h = (idx >> 5) & 15;
    const int s = (idx >> 9) & 1;
    const int n = (idx >> 10) & 2047;
    const int b = idx >> 21;

    // inv_freq = 10000^(-j/32)
    const float inv_freq = expf(-(float)j * (9.210340371976184f / 32.0f));
    const float theta = (float)n * inv_freq;
    float sn, cs;
    sincosf(theta, &sn, &cs);

    const size_t base = ((size_t)(b * SEQ + n) * 3 + s) * DIMC + h * HD;
    const float x0 = qkv[base + j];
    const float x1 = qkv[base + j + 32];
    qkv[base + j]      = x0 * cs - x1 * sn;
    qkv[base + j + 32] = x1 * cs + x0 * sn;
}

// ---------------------------------------------------------------------------
// Fused flash attention (non-causal), fp32, online softmax.
// Grid: (SEQ/64, BATCH*NH). 256 threads. 64 query rows per block, 64-key tiles.
// Per-thread: 4 rows (ty) x 4 key-cols / 4 out-cols (tx), f32x2-packed GEMM phases.
// smem: Qs[d][r] 16KB + KP (K[d][j] then P[r][j]) 16KB + Vs[j][c] 16KB = 48KB.
// ---------------------------------------------------------------------------
__global__ __launch_bounds__(256) void attn_kernel(
    const float* __restrict__ qkv, float* __restrict__ out)
{
    __shared__ float Qs[64 * 64];
    __shared__ float KP[64 * 64];
    __shared__ float Vs[64 * 64];

    const int tid = threadIdx.x;
    const int tx = tid & 15;
    const int ty = tid >> 4;
    const int n0 = blockIdx.x * 64;
    const int bh = blockIdx.y;
    const int b = bh >> 4;
    const int h = bh & 15;
    const float scale = 0.125f;   // 1/sqrt(64)

    const float* qbase = qkv + (size_t)(b * SEQ) * 3 * DIMC + h * HD;
    const float* kbase = qbase + DIMC;
    const float* vbase = qbase + 2 * DIMC;

    // Load Q tile transposed: Qs[d][r]
#pragma unroll
    for (int t = 0; t < 4; t++) {
        const int idx = tid + t * 256;
        const int row = idx >> 4;
        const int c4  = (idx & 15) * 4;
        const float4 qv = *(const float4*)(qbase + (size_t)(n0 + row) * (3 * DIMC) + c4);
        Qs[(c4 + 0) * 64 + row] = qv.x;
        Qs[(c4 + 1) * 64 + row] = qv.y;
        Qs[(c4 + 2) * 64 + row] = qv.z;
        Qs[(c4 + 3) * 64 + row] = qv.w;
    }

    float m_i[4], l_i[4];
    unsigned long long o2[4][2];
#pragma unroll
    for (int i = 0; i < 4; i++) {
        m_i[i] = -1e30f;
        l_i[i] = 0.0f;
        o2[i][0] = 0ull;
        o2[i][1] = 0ull;
    }

    for (int k0 = 0; k0 < SEQ; k0 += 64) {
        // Load K tile transposed into KP, V tile natural into Vs
#pragma unroll
        for (int t = 0; t < 4; t++) {
            const int idx = tid + t * 256;
            const int row = idx >> 4;
            const int c4  = (idx & 15) * 4;
            const size_t goff = (size_t)(k0 + row) * (3 * DIMC) + c4;
            const float4 kv = *(const float4*)(kbase + goff);
            KP[(c4 + 0) * 64 + row] = kv.x;
            KP[(c4 + 1) * 64 + row] = kv.y;
            KP[(c4 + 2) * 64 + row] = kv.z;
            KP[(c4 + 3) * 64 + row] = kv.w;
            const float4 vv = *(const float4*)(vbase + goff);
            *(float4*)&Vs[row * 64 + c4] = vv;
        }
        __syncthreads();

        // S[r][j] = sum_d Q[r][d] K[j][d]   (packed over j-pairs)
        unsigned long long s2[4][2];
#pragma unroll
        for (int i = 0; i < 4; i++) { s2[i][0] = 0ull; s2[i][1] = 0ull; }
#pragma unroll 4
        for (int d = 0; d < 64; d++) {
            const float4 a4 = *(const float4*)&Qs[d * 64 + ty * 4];
            const ulonglong2 kq = *(const ulonglong2*)&KP[d * 64 + tx * 4];
            unsigned long long ad[4] = {dup2(a4.x), dup2(a4.y), dup2(a4.z), dup2(a4.w)};
#pragma unroll
            for (int i = 0; i < 4; i++) {
                s2[i][0] = ffma2(ad[i], kq.x, s2[i][0]);
                s2[i][1] = ffma2(ad[i], kq.y, s2[i][1]);
            }
        }

        // Online softmax update (register + warp-shuffle; rows live in 16-lane
        // groups: lanes with the same ty are contiguous lanes of one warp)
        float p[4][4];
#pragma unroll
        for (int i = 0; i < 4; i++) {
            float2 v0 = unpk2(s2[i][0]);
            float2 v1 = unpk2(s2[i][1]);
            float sv0 = v0.x * scale, sv1 = v0.y * scale;
            float sv2 = v1.x * scale, sv3 = v1.y * scale;
            float mx = fmaxf(fmaxf(sv0, sv1), fmaxf(sv2, sv3));
#pragma unroll
            for (int off = 8; off >= 1; off >>= 1)
                mx = fmaxf(mx, __shfl_xor_sync(0xffffffffu, mx, off));
            const float mnew = fmaxf(m_i[i], mx);
            p[i][0] = __expf(sv0 - mnew);
            p[i][1] = __expf(sv1 - mnew);
            p[i][2] = __expf(sv2 - mnew);
            p[i][3] = __expf(sv3 - mnew);
            float sum = p[i][0] + p[i][1] + p[i][2] + p[i][3];
#pragma unroll
            for (int off = 8; off >= 1; off >>= 1)
                sum += __shfl_xor_sync(0xffffffffu, sum, off);
            const float alpha = __expf(m_i[i] - mnew);
            l_i[i] = l_i[i] * alpha + sum;
            m_i[i] = mnew;
            const unsigned long long a2 = dup2(alpha);
            o2[i][0] = ffma2(a2, o2[i][0], 0ull);
            o2[i][1] = ffma2(a2, o2[i][1], 0ull);
        }
        __syncthreads();   // all S reads of KP done before overwriting with P

        // Store P into KP as [r][j]
#pragma unroll
        for (int i = 0; i < 4; i++) {
            *(float4*)&KP[(ty * 4 + i) * 64 + tx * 4] =
                make_float4(p[i][0], p[i][1], p[i][2], p[i][3]);
        }
        __syncthreads();

        // O[r][c] += sum_j P[r][j] V[j][c]   (packed over c-pairs)
#pragma unroll 4
        for (int j = 0; j < 64; j++) {
            float a0 = KP[(ty * 4 + 0) * 64 + j];
            float a1 = KP[(ty * 4 + 1) * 64 + j];
            float a2v = KP[(ty * 4 + 2) * 64 + j];
            float a3 = KP[(ty * 4 + 3) * 64 + j];
            const ulonglong2 vq = *(const ulonglong2*)&Vs[j * 64 + tx * 4];
            unsigned long long d0 = dup2(a0), d1 = dup2(a1), d2 = dup2(a2v), d3 = dup2(a3);
            o2[0][0] = ffma2(d0, vq.x, o2[0][0]);
            o2[0][1] = ffma2(d0, vq.y, o2[0][1]);
            o2[1][0] = ffma2(d1, vq.x, o2[1][0]);
            o2[1][1] = ffma2(d1, vq.y, o2[1][1]);
            o2[2][0] = ffma2(d2, vq.x, o2[2][0]);
            o2[2][1] = ffma2(d2, vq.y, o2[2][1]);
            o2[3][0] = ffma2(d3, vq.x, o2[3][0]);
            o2[3][1] = ffma2(d3, vq.y, o2[3][1]);
        }
        __syncthreads();
    }

    // Epilogue: normalize by l, write [B,N,H*D]
#pragma unroll
    for (int i = 0; i < 4; i++) {
        const float inv = 1.0f / l_i[i];
        float2 v0 = unpk2(o2[i][0]);
        float2 v1 = unpk2(o2[i][1]);
        float4 r = make_float4(v0.x * inv, v0.y * inv, v1.x * inv, v1.y * inv);
        *(float4*)&out[(size_t)(b * SEQ + n0 + ty * 4 + i) * DIMC + h * HD + tx * 4] = r;
    }
}

// ---------------------------------------------------------------------------
// SwiGLU elementwise: out = silu(x1) * x2
// ---------------------------------------------------------------------------
__global__ void silu_mul_kernel(const float* __restrict__ x1,
                                const float* __restrict__ x2,
                                float* __restrict__ out, int n)
{
    const int i = blockIdx.x * blockDim.x + threadIdx.x;
    if (i < n) {
        const float a = x1[i];
        const float bb = x2[i];
        out[i] = (a / (1.0f + expf(-a))) * bb;
    }
}

// ---------------------------------------------------------------------------
// kernel_launch
// ---------------------------------------------------------------------------
extern "C" void kernel_launch(void* const* d_in, const int* in_sizes, int n_in,
                              void* d_out, int out_size)
{
    const float* x      = (const float*)d_in[0];
    const float* qkv_w  = (const float*)d_in[1];
    const float* proj_w = (const float*)d_in[2];
    const float* proj_b = (const float*)d_in[3];
    const float* w1_w   = (const float*)d_in[4];
    const float* w1_b   = (const float*)d_in[5];
    const float* w2_w   = (const float*)d_in[6];
    const float* w2_b   = (const float*)d_in[7];
    const float* w3_w   = (const float*)d_in[8];
    const float* w3_b   = (const float*)d_in[9];
    float* out = (float*)d_out;

    float *qkv, *attn, *proj, *x1, *x2;
    cudaGetSymbolAddress((void**)&qkv,  g_qkv);
    cudaGetSymbolAddress((void**)&attn, g_attn);
    cudaGetSymbolAddress((void**)&proj, g_proj);
    cudaGetSymbolAddress((void**)&x1,   g_x1);
    cudaGetSymbolAddress((void**)&x2,   g_x2);

    // 1) QKV projection: [8192,1024] @ [3072,1024]^T -> [8192,3072]
    gemm_nt_kernel<<<dim3(3 * DIMC / GBN, MTOK / GBM), 256>>>(
        x, qkv_w, nullptr, qkv, MTOK, 3 * DIMC, DIMC);

    // 2) RoPE on q,k slices (2^23 pairs)
    rope_kernel<<<(BATCH * SEQ * 2 * NH * (HD / 2)) / 256, 256>>>(qkv);

    // 3) Fused attention -> [8192,1024]
    attn_kernel<<<dim3(SEQ / 64, BATCH * NH), 256>>>(qkv, attn);

    // 4) Output projection + bias
    gemm_nt_kernel<<<dim3(DIMC / GBN, MTOK / GBM), 256>>>(
        attn, proj_w, proj_b, proj, MTOK, DIMC, DIMC);

    // 5) MLP up projections
    gemm_nt_kernel<<<dim3(HID / GBN, MTOK / GBM), 256>>>(
        proj, w1_w, w1_b, x1, MTOK, HID, DIMC);
    gemm_nt_kernel<<<dim3(HID / GBN, MTOK / GBM), 256>>>(
        proj, w2_w, w2_b, x2, MTOK, HID, DIMC);

    // 6) SwiGLU elementwise (in-place into x1)
    silu_mul_kernel<<<(MTOK * HID + 255) / 256, 256>>>(x1, x2, x1, MTOK * HID);

    // 7) Down projection -> d_out
    gemm_nt_kernel<<<dim3(DIMC / GBN, MTOK / GBM), 256>>>(
        x1, w3_w, w3_b, out, MTOK, DIMC, HID);
}

// round 5
// speedup vs baseline: 2.2501x; 2.2501x over previous
#include <cuda_runtime.h>
#include <cuda_bf16.h>
#include <math.h>

// Problem constants
#define BATCH 4
#define SEQ   2048
#define DIMC  1024
#define NH    16
#define HD    64
#define HID   2048
#define MTOK  (BATCH * SEQ)   // 8192 tokens

// ===========================================================================
// Scratch (static device globals; allocations forbidden)
// ===========================================================================
__device__ float g_qkv[(size_t)MTOK * 3 * DIMC];   // fp32 for rope+attention
__device__ float g_x1[(size_t)MTOK * HID];
__device__ float g_x2[(size_t)MTOK * HID];

// K-concatenated split-bf16 operands:  A' = [hi | lo | hi],  B' = [hi | hi | lo]
__device__ __align__(256) __nv_bfloat16 g_xc[(size_t)MTOK * 3 * DIMC];      // x split
__device__ __align__(256) __nv_bfloat16 g_attnc[(size_t)MTOK * 3 * DIMC];   // attn out
__device__ __align__(256) __nv_bfloat16 g_projc[(size_t)MTOK * 3 * DIMC];   // proj out
__device__ __align__(256) __nv_bfloat16 g_hc[(size_t)MTOK * 3 * HID];       // swiglu out
__device__ __align__(256) __nv_bfloat16 g_wqkvc[(size_t)3 * DIMC * 3 * DIMC];
__device__ __align__(256) __nv_bfloat16 g_wprojc[(size_t)DIMC * 3 * DIMC];
__device__ __align__(256) __nv_bfloat16 g_w1c[(size_t)HID * 3 * DIMC];
__device__ __align__(256) __nv_bfloat16 g_w2c[(size_t)HID * 3 * DIMC];
__device__ __align__(256) __nv_bfloat16 g_w3c[(size_t)DIMC * 3 * HID];

// ===========================================================================
// Helpers
// ===========================================================================
__device__ __forceinline__ unsigned smem_to_u32(const void* p) {
    unsigned a;
    asm("{ .reg .u64 t; cvta.to.shared.u64 t, %1; cvt.u32.u64 %0, t; }"
        : "=r"(a) : "l"(p));
    return a;
}
__device__ __forceinline__ void cp_async16(unsigned dst, const void* src) {
    asm volatile("cp.async.cg.shared.global [%0], [%1], 16;" :: "r"(dst), "l"(src));
}
__device__ __forceinline__ void cp_commit() {
    asm volatile("cp.async.commit_group;" ::: "memory");
}
template <int N>
__device__ __forceinline__ void cp_wait() {
    asm volatile("cp.async.wait_group %0;" :: "n"(N) : "memory");
}
__device__ __forceinline__ void ldm4(unsigned* r, unsigned addr) {
    asm volatile("ldmatrix.sync.aligned.m8n8.x4.shared.b16 {%0,%1,%2,%3}, [%4];"
        : "=r"(r[0]), "=r"(r[1]), "=r"(r[2]), "=r"(r[3]) : "r"(addr));
}
__device__ __forceinline__ void mma16816(float* d, const unsigned* a,
                                         unsigned b0, unsigned b1) {
    asm volatile(
        "mma.sync.aligned.m16n8k16.row.col.f32.bf16.bf16.f32 "
        "{%0,%1,%2,%3}, {%4,%5,%6,%7}, {%8,%9}, {%0,%1,%2,%3};"
        : "+f"(d[0]), "+f"(d[1]), "+f"(d[2]), "+f"(d[3])
        : "r"(a[0]), "r"(a[1]), "r"(a[2]), "r"(a[3]), "r"(b0), "r"(b1));
}
__device__ __forceinline__ unsigned pack_bf2(__nv_bfloat16 a, __nv_bfloat16 b) {
    unsigned short ua = *(unsigned short*)&a;
    unsigned short ub = *(unsigned short*)&b;
    return (unsigned)ua | ((unsigned)ub << 16);
}

// ===========================================================================
// Split kernels: fp32 -> K-concatenated bf16 hi/lo
//   A-type: [hi | lo | hi]     B-type: [hi | hi | lo]
// ===========================================================================
__global__ void split_a_kernel(const float* __restrict__ in,
                               __nv_bfloat16* __restrict__ out, int K, int n)
{
    const int i = blockIdx.x * blockDim.x + threadIdx.x;
    if (i < n) {
        const int r = i / K, k = i - r * K;
        const float v = in[i];
        const __nv_bfloat16 h = __float2bfloat16(v);
        const __nv_bfloat16 l = __float2bfloat16(v - __bfloat162float(h));
        __nv_bfloat16* o = out + (size_t)r * 3 * K + k;
        o[0] = h; o[K] = l; o[2 * K] = h;
    }
}
__global__ void split_b_kernel(const float* __restrict__ in,
                               __nv_bfloat16* __restrict__ out, int K, int n)
{
    const int i = blockIdx.x * blockDim.x + threadIdx.x;
    if (i < n) {
        const int r = i / K, k = i - r * K;
        const float v = in[i];
        const __nv_bfloat16 h = __float2bfloat16(v);
        const __nv_bfloat16 l = __float2bfloat16(v - __bfloat162float(h));
        __nv_bfloat16* o = out + (size_t)r * 3 * K + k;
        o[0] = h; o[K] = h; o[2 * K] = l;
    }
}

// ===========================================================================
// bf16 tensor-core NT GEMM via mma.sync:
//   C[M,N] = A'[M,K'] @ B'[N,K']^T (+ bias[N])
// BM=128, BN=128, BK=64, 4-stage cp.async pipeline, 256 threads (8 warps).
// Warp tile 64x32 (2x4 warp grid), mma m16n8k16.
// Output: fp32 (outf, stride N) and/or concat-split bf16 (outc, stride 3N).
// ===========================================================================
#define BM 128
#define BN 128
#define BK 64
#define STAGES 4
#define A_BYTES (BM * BK * 2)           // 16 KB
#define B_BYTES (BN * BK * 2)           // 16 KB
#define STG_BYTES (A_BYTES + B_BYTES)   // 32 KB
#define GSMEM_SZ (STAGES * STG_BYTES)   // 128 KB

__global__ __launch_bounds__(256, 1) void gemm_mma_kernel(
    const __nv_bfloat16* __restrict__ A, const __nv_bfloat16* __restrict__ B,
    const float* __restrict__ bias,
    float* __restrict__ outf, __nv_bfloat16* __restrict__ outc,
    int N, int K)
{
    extern __shared__ char sm[];
    const unsigned sbase = smem_to_u32(sm);
    const int tid = threadIdx.x;
    const int wid = tid >> 5;
    const int lane = tid & 31;
    const int m0 = blockIdx.y * BM;
    const int n0 = blockIdx.x * BN;
    const int mw = (wid & 1) * 64;     // warp m-offset in tile
    const int nw = (wid >> 1) * 32;    // warp n-offset in tile

    float acc[4][4][4];
#pragma unroll
    for (int a = 0; a < 4; a++)
#pragma unroll
        for (int b = 0; b < 4; b++)
#pragma unroll
            for (int c = 0; c < 4; c++) acc[a][b][c] = 0.0f;

    // Per-thread load assignment: 4 A-chunks + 4 B-chunks of 16B per stage
    const int lrow = tid >> 1;                 // unused placeholder
    (void)lrow;

#define LOAD_STAGE(st, k0)                                                      \
    do {                                                                        \
        const unsigned s_a = sbase + (unsigned)(st) * STG_BYTES;                \
        const unsigned s_b = s_a + A_BYTES;                                     \
        _Pragma("unroll")                                                       \
        for (int i = 0; i < 4; i++) {                                           \
            const int idx = tid + i * 256;                                      \
            const int row = idx >> 3, ch = idx & 7;                             \
            cp_async16(s_a + row * 128 + ((ch ^ (row & 7)) << 4),               \
                       A + (size_t)(m0 + row) * K + (k0) + ch * 8);             \
        }                                                                       \
        _Pragma("unroll")                                                       \
        for (int i = 0; i < 4; i++) {                                           \
            const int idx = tid + i * 256;                                      \
            const int row = idx >> 3, ch = idx & 7;                             \
            cp_async16(s_b + row * 128 + ((ch ^ (row & 7)) << 4),               \
                       B + (size_t)(n0 + row) * K + (k0) + ch * 8);             \
        }                                                                       \
    } while (0)

    const int NK = K / BK;
#pragma unroll
    for (int s = 0; s < STAGES - 1; s++) {
        LOAD_STAGE(s, s * BK);
        cp_commit();
    }

    for (int ks = 0; ks < NK; ks++) {
        cp_wait<STAGES - 2>();
        __syncthreads();

        const int ns = ks + STAGES - 1;
        if (ns < NK) { LOAD_STAGE(ns & (STAGES - 1), ns * BK); }
        cp_commit();

        const unsigned s_a = sbase + (unsigned)(ks & (STAGES - 1)) * STG_BYTES;
        const unsigned s_b = s_a + A_BYTES;

#pragma unroll
        for (int kk = 0; kk < 4; kk++) {
            unsigned a_r[4][4], b_r[2][4];
#pragma unroll
            for (int mt = 0; mt < 4; mt++) {
                const int r = mw + mt * 16 + (lane & 15);
                const int cch = kk * 2 + (lane >> 4);
                ldm4(a_r[mt], s_a + r * 128 + ((cch ^ (r & 7)) << 4));
            }
#pragma unroll
            for (int ng = 0; ng < 2; ng++) {
                const int r = nw + ng * 16 + (lane & 7) + ((lane >> 4) << 3);
                const int cch = kk * 2 + ((lane >> 3) & 1);
                ldm4(b_r[ng], s_b + r * 128 + ((cch ^ (r & 7)) << 4));
            }
#pragma unroll
            for (int mt = 0; mt < 4; mt++) {
#pragma unroll
                for (int nt = 0; nt < 4; nt++) {
                    mma16816(acc[mt][nt], a_r[mt],
                             b_r[nt >> 1][(nt & 1) * 2],
                             b_r[nt >> 1][(nt & 1) * 2 + 1]);
                }
            }
        }
    }
    cp_wait<0>();

    // Epilogue
#pragma unroll
    for (int mt = 0; mt < 4; mt++) {
#pragma unroll
        for (int nt = 0; nt < 4; nt++) {
            const int row0 = m0 + mw + mt * 16 + (lane >> 2);
            const int col  = n0 + nw + nt * 8 + (lane & 3) * 2;
            float bv0 = 0.0f, bv1 = 0.0f;
            if (bias != nullptr) { bv0 = bias[col]; bv1 = bias[col + 1]; }
#pragma unroll
            for (int h = 0; h < 2; h++) {
                const int row = row0 + h * 8;
                const float v0 = acc[mt][nt][h * 2 + 0] + bv0;
                const float v1 = acc[mt][nt][h * 2 + 1] + bv1;
                if (outf != nullptr) {
                    *(float2*)&outf[(size_t)row * N + col] = make_float2(v0, v1);
                }
                if (outc != nullptr) {
                    const __nv_bfloat16 h0 = __float2bfloat16(v0);
                    const __nv_bfloat16 h1 = __float2bfloat16(v1);
                    const __nv_bfloat16 l0 = __float2bfloat16(v0 - __bfloat162float(h0));
                    const __nv_bfloat16 l1 = __float2bfloat16(v1 - __bfloat162float(h1));
                    const size_t base = (size_t)row * 3 * N + col;
                    *(unsigned*)&outc[base]         = pack_bf2(h0, h1);
                    *(unsigned*)&outc[base + N]     = pack_bf2(l0, l1);
                    *(unsigned*)&outc[base + 2 * N] = pack_bf2(h0, h1);
                }
            }
        }
    }
#undef LOAD_STAGE
}

// ===========================================================================
// RoPE (in-place on q,k slices of g_qkv) — fp32-exact
// ===========================================================================
__global__ void rope_kernel(float* __restrict__ qkv)
{
    const int idx = blockIdx.x * blockDim.x + threadIdx.x;
    const int j = idx & 31;
    const int hh = (idx >> 5) & 15;
    const int s = (idx >> 9) & 1;
    const int n = (idx >> 10) & 2047;
    const int b = idx >> 21;

    const float inv_freq = expf(-(float)j * (9.210340371976184f / 32.0f));
    const float theta = (float)n * inv_freq;
    float sn, cs;
    sincosf(theta, &sn, &cs);

    const size_t base = ((size_t)(b * SEQ + n) * 3 + s) * DIMC + hh * HD;
    const float x0 = qkv[base + j];
    const float x1 = qkv[base + j + 32];
    qkv[base + j]      = x0 * cs - x1 * sn;
    qkv[base + j + 32] = x1 * cs + x0 * sn;
}

// ===========================================================================
// fp32x2 helpers for attention
// ===========================================================================
__device__ __forceinline__ unsigned long long ffma2(unsigned long long a,
                                                    unsigned long long b,
                                                    unsigned long long c) {
    unsigned long long d;
    asm("fma.rn.f32x2 %0, %1, %2, %3;" : "=l"(d) : "l"(a), "l"(b), "l"(c));
    return d;
}
__device__ __forceinline__ unsigned long long dup2(float a) {
    unsigned long long d;
    asm("mov.b64 %0, {%1, %1};" : "=l"(d) : "f"(a));
    return d;
}
__device__ __forceinline__ float2 unpk2(unsigned long long v) {
    float lo, hi;
    asm("mov.b64 {%0, %1}, %2;" : "=f"(lo), "=f"(hi) : "l"(v));
    return make_float2(lo, hi);
}

// ===========================================================================
// Fused flash attention (non-causal), fp32; epilogue writes concat split bf16
// ===========================================================================
__global__ __launch_bounds__(256) void attn_kernel(
    const float* __restrict__ qkv, __nv_bfloat16* __restrict__ outc)
{
    __shared__ float Qs[64 * 64];
    __shared__ float KP[64 * 64];
    __shared__ float Vs[64 * 64];

    const int tid = threadIdx.x;
    const int tx = tid & 15;
    const int ty = tid >> 4;
    const int n0 = blockIdx.x * 64;
    const int bh = blockIdx.y;
    const int b = bh >> 4;
    const int hh = bh & 15;
    const float scale = 0.125f;

    const float* qbase = qkv + (size_t)(b * SEQ) * 3 * DIMC + hh * HD;
    const float* kbase = qbase + DIMC;
    const float* vbase = qbase + 2 * DIMC;

#pragma unroll
    for (int t = 0; t < 4; t++) {
        const int idx = tid + t * 256;
        const int row = idx >> 4;
        const int c4  = (idx & 15) * 4;
        const float4 qv = *(const float4*)(qbase + (size_t)(n0 + row) * (3 * DIMC) + c4);
        Qs[(c4 + 0) * 64 + row] = qv.x;
        Qs[(c4 + 1) * 64 + row] = qv.y;
        Qs[(c4 + 2) * 64 + row] = qv.z;
        Qs[(c4 + 3) * 64 + row] = qv.w;
    }

    float m_i[4], l_i[4];
    unsigned long long o2[4][2];
#pragma unroll
    for (int i = 0; i < 4; i++) {
        m_i[i] = -1e30f; l_i[i] = 0.0f;
        o2[i][0] = 0ull; o2[i][1] = 0ull;
    }

    for (int k0 = 0; k0 < SEQ; k0 += 64) {
#pragma unroll
        for (int t = 0; t < 4; t++) {
            const int idx = tid + t * 256;
            const int row = idx >> 4;
            const int c4  = (idx & 15) * 4;
            const size_t goff = (size_t)(k0 + row) * (3 * DIMC) + c4;
            const float4 kv = *(const float4*)(kbase + goff);
            KP[(c4 + 0) * 64 + row] = kv.x;
            KP[(c4 + 1) * 64 + row] = kv.y;
            KP[(c4 + 2) * 64 + row] = kv.z;
            KP[(c4 + 3) * 64 + row] = kv.w;
            const float4 vv = *(const float4*)(vbase + goff);
            *(float4*)&Vs[row * 64 + c4] = vv;
        }
        __syncthreads();

        unsigned long long s2[4][2];
#pragma unroll
        for (int i = 0; i < 4; i++) { s2[i][0] = 0ull; s2[i][1] = 0ull; }
#pragma unroll 4
        for (int d = 0; d < 64; d++) {
            const float4 a4 = *(const float4*)&Qs[d * 64 + ty * 4];
            const ulonglong2 kq = *(const ulonglong2*)&KP[d * 64 + tx * 4];
            unsigned long long ad[4] = {dup2(a4.x), dup2(a4.y), dup2(a4.z), dup2(a4.w)};
#pragma unroll
            for (int i = 0; i < 4; i++) {
                s2[i][0] = ffma2(ad[i], kq.x, s2[i][0]);
                s2[i][1] = ffma2(ad[i], kq.y, s2[i][1]);
            }
        }

        float p[4][4];
#pragma unroll
        for (int i = 0; i < 4; i++) {
            float2 v0 = unpk2(s2[i][0]);
            float2 v1 = unpk2(s2[i][1]);
            float sv0 = v0.x * scale, sv1 = v0.y * scale;
            float sv2 = v1.x * scale, sv3 = v1.y * scale;
            float mx = fmaxf(fmaxf(sv0, sv1), fmaxf(sv2, sv3));
#pragma unroll
            for (int off = 8; off >= 1; off >>= 1)
                mx = fmaxf(mx, __shfl_xor_sync(0xffffffffu, mx, off));
            const float mnew = fmaxf(m_i[i], mx);
            p[i][0] = __expf(sv0 - mnew);
            p[i][1] = __expf(sv1 - mnew);
            p[i][2] = __expf(sv2 - mnew);
            p[i][3] = __expf(sv3 - mnew);
            float sum = p[i][0] + p[i][1] + p[i][2] + p[i][3];
#pragma unroll
            for (int off = 8; off >= 1; off >>= 1)
                sum += __shfl_xor_sync(0xffffffffu, sum, off);
            const float alpha = __expf(m_i[i] - mnew);
            l_i[i] = l_i[i] * alpha + sum;
            m_i[i] = mnew;
            const unsigned long long a2 = dup2(alpha);
            o2[i][0] = ffma2(a2, o2[i][0], 0ull);
            o2[i][1] = ffma2(a2, o2[i][1], 0ull);
        }
        __syncthreads();

#pragma unroll
        for (int i = 0; i < 4; i++) {
            *(float4*)&KP[(ty * 4 + i) * 64 + tx * 4] =
                make_float4(p[i][0], p[i][1], p[i][2], p[i][3]);
        }
        __syncthreads();

#pragma unroll 4
        for (int j = 0; j < 64; j++) {
            float a0 = KP[(ty * 4 + 0) * 64 + j];
            float a1 = KP[(ty * 4 + 1) * 64 + j];
            float a2v = KP[(ty * 4 + 2) * 64 + j];
            float a3 = KP[(ty * 4 + 3) * 64 + j];
            const ulonglong2 vq = *(const ulonglong2*)&Vs[j * 64 + tx * 4];
            unsigned long long d0 = dup2(a0), d1 = dup2(a1), d2 = dup2(a2v), d3 = dup2(a3);
            o2[0][0] = ffma2(d0, vq.x, o2[0][0]);
            o2[0][1] = ffma2(d0, vq.y, o2[0][1]);
            o2[1][0] = ffma2(d1, vq.x, o2[1][0]);
            o2[1][1] = ffma2(d1, vq.y, o2[1][1]);
            o2[2][0] = ffma2(d2, vq.x, o2[2][0]);
            o2[2][1] = ffma2(d2, vq.y, o2[2][1]);
            o2[3][0] = ffma2(d3, vq.x, o2[3][0]);
            o2[3][1] = ffma2(d3, vq.y, o2[3][1]);
        }
        __syncthreads();
    }

    // Epilogue: normalize, write K-concat split bf16 (segments of DIMC)
#pragma unroll
    for (int i = 0; i < 4; i++) {
        const float inv = 1.0f / l_i[i];
        float2 v0 = unpk2(o2[i][0]);
        float2 v1 = unpk2(o2[i][1]);
        float vals[4] = {v0.x * inv, v0.y * inv, v1.x * inv, v1.y * inv};
        __nv_bfloat16 hi[4], lo[4];
#pragma unroll
        for (int t = 0; t < 4; t++) {
            hi[t] = __float2bfloat16(vals[t]);
            lo[t] = __float2bfloat16(vals[t] - __bfloat162float(hi[t]));
        }
        const size_t base =
            (size_t)(b * SEQ + n0 + ty * 4 + i) * (3 * DIMC) + hh * HD + tx * 4;
        *(unsigned*)&outc[base]            = pack_bf2(hi[0], hi[1]);
        *(unsigned*)&outc[base + 2]        = pack_bf2(hi[2], hi[3]);
        *(unsigned*)&outc[base + DIMC]     = pack_bf2(lo[0], lo[1]);
        *(unsigned*)&outc[base + DIMC + 2] = pack_bf2(lo[2], lo[3]);
        *(unsigned*)&outc[base + 2*DIMC]   = pack_bf2(hi[0], hi[1]);
        *(unsigned*)&outc[base + 2*DIMC+2] = pack_bf2(hi[2], hi[3]);
    }
}

// ===========================================================================
// SwiGLU elementwise -> concat split bf16 (segments of HID)
// ===========================================================================
__global__ void silu_split_kernel(const float* __restrict__ x1,
                                  const float* __restrict__ x2,
                                  __nv_bfloat16* __restrict__ outc, int n)
{
    const int i = blockIdx.x * blockDim.x + threadIdx.x;
    if (i < n) {
        const int r = i / HID, k = i - r * HID;
        const float a = x1[i];
        const float v = (a / (1.0f + expf(-a))) * x2[i];
        const __nv_bfloat16 h = __float2bfloat16(v);
        const __nv_bfloat16 l = __float2bfloat16(v - __bfloat162float(h));
        __nv_bfloat16* o = outc + (size_t)r * 3 * HID + k;
        o[0] = h; o[HID] = l; o[2 * HID] = h;
    }
}

// ===========================================================================
// kernel_launch
// ===========================================================================
extern "C" void kernel_launch(void* const* d_in, const int* in_sizes, int n_in,
                              void* d_out, int out_size)
{
    const float* x      = (const float*)d_in[0];
    const float* qkv_w  = (const float*)d_in[1];
    const float* proj_w = (const float*)d_in[2];
    const float* proj_b = (const float*)d_in[3];
    const float* w1_w   = (const float*)d_in[4];
    const float* w1_b   = (const float*)d_in[5];
    const float* w2_w   = (const float*)d_in[6];
    const float* w2_b   = (const float*)d_in[7];
    const float* w3_w   = (const float*)d_in[8];
    const float* w3_b   = (const float*)d_in[9];
    float* out = (float*)d_out;

    cudaFuncSetAttribute(gemm_mma_kernel,
                         cudaFuncAttributeMaxDynamicSharedMemorySize, GSMEM_SZ);

    float *qkv, *x1, *x2;
    cudaGetSymbolAddress((void**)&qkv, g_qkv);
    cudaGetSymbolAddress((void**)&x1,  g_x1);
    cudaGetSymbolAddress((void**)&x2,  g_x2);
    __nv_bfloat16 *xc, *attnc, *projc, *hc, *wqkvc, *wprojc, *w1c, *w2c, *w3c;
    cudaGetSymbolAddress((void**)&xc,    g_xc);
    cudaGetSymbolAddress((void**)&attnc, g_attnc);
    cudaGetSymbolAddress((void**)&projc, g_projc);
    cudaGetSymbolAddress((void**)&hc,    g_hc);
    cudaGetSymbolAddress((void**)&wqkvc, g_wqkvc);
    cudaGetSymbolAddress((void**)&wprojc,g_wprojc);
    cudaGetSymbolAddress((void**)&w1c,   g_w1c);
    cudaGetSymbolAddress((void**)&w2c,   g_w2c);
    cudaGetSymbolAddress((void**)&w3c,   g_w3c);

    // Splits (x is A-type; all weights are B-type)
    split_a_kernel<<<(MTOK * DIMC) / 256, 256>>>(x, xc, DIMC, MTOK * DIMC);
    split_b_kernel<<<(3 * DIMC * DIMC) / 256, 256>>>(qkv_w, wqkvc, DIMC, 3 * DIMC * DIMC);
    split_b_kernel<<<(DIMC * DIMC) / 256, 256>>>(proj_w, wprojc, DIMC, DIMC * DIMC);
    split_b_kernel<<<(HID * DIMC) / 256, 256>>>(w1_w, w1c, DIMC, HID * DIMC);
    split_b_kernel<<<(HID * DIMC) / 256, 256>>>(w2_w, w2c, DIMC, HID * DIMC);
    split_b_kernel<<<(DIMC * HID) / 256, 256>>>(w3_w, w3c, HID, DIMC * HID);

    // 1) QKV projection: K'=3072, N=3072 -> fp32
    gemm_mma_kernel<<<dim3(3 * DIMC / BN, MTOK / BM), 256, GSMEM_SZ>>>(
        xc, wqkvc, nullptr, qkv, nullptr, 3 * DIMC, 3 * DIMC);

    // 2) RoPE
    rope_kernel<<<(BATCH * SEQ * 2 * NH * (HD / 2)) / 256, 256>>>(qkv);

    // 3) Attention -> concat split bf16
    attn_kernel<<<dim3(SEQ / 64, BATCH * NH), 256>>>(qkv, attnc);

    // 4) Output projection (+bias): K'=3072, N=1024 -> concat split bf16
    gemm_mma_kernel<<<dim3(DIMC / BN, MTOK / BM), 256, GSMEM_SZ>>>(
        attnc, wprojc, proj_b, nullptr, projc, DIMC, 3 * DIMC);

    // 5) MLP up projections: K'=3072, N=2048 -> fp32
    gemm_mma_kernel<<<dim3(HID / BN, MTOK / BM), 256, GSMEM_SZ>>>(
        projc, w1c, w1_b, x1, nullptr, HID, 3 * DIMC);
    gemm_mma_kernel<<<dim3(HID / BN, MTOK / BM), 256, GSMEM_SZ>>>(
        projc, w2c, w2_b, x2, nullptr, HID, 3 * DIMC);

    // 6) SwiGLU -> concat split bf16
    silu_split_kernel<<<(MTOK * HID) / 256, 256>>>(x1, x2, hc, MTOK * HID);

    // 7) Down projection: K'=6144, N=1024 -> fp32 out
    gemm_mma_kernel<<<dim3(DIMC / BN, MTOK / BM), 256, GSMEM_SZ>>>(
        hc, w3c, w3_b, out, nullptr, DIMC, 3 * HID);
}

// round 6
// speedup vs baseline: 3.5973x; 1.5987x over previous
#include <cuda_runtime.h>
#include <cuda_bf16.h>
#include <math.h>

// Problem constants
#define BATCH 4
#define SEQ   2048
#define DIMC  1024
#define NH    16
#define HD    64
#define HID   2048
#define MTOK  (BATCH * SEQ)   // 8192 tokens

// ===========================================================================
// Scratch (static device globals; allocations forbidden)
// ===========================================================================
__device__ float g_qkv[(size_t)MTOK * 3 * DIMC];   // fp32 qkv (pre-rope)
__device__ float g_x1[(size_t)MTOK * HID];
__device__ float g_x2[(size_t)MTOK * HID];

// K-concatenated split-bf16 operands:  A' = [hi | lo | hi],  B' = [hi | hi | lo]
__device__ __align__(256) __nv_bfloat16 g_xc[(size_t)MTOK * 3 * DIMC];      // x split
__device__ __align__(256) __nv_bfloat16 g_attnc[(size_t)MTOK * 3 * DIMC];   // attn out
__device__ __align__(256) __nv_bfloat16 g_projc[(size_t)MTOK * 3 * DIMC];   // proj out
__device__ __align__(256) __nv_bfloat16 g_hc[(size_t)MTOK * 3 * HID];       // swiglu out
__device__ __align__(256) __nv_bfloat16 g_wqkvc[(size_t)3 * DIMC * 3 * DIMC];
__device__ __align__(256) __nv_bfloat16 g_wprojc[(size_t)DIMC * 3 * DIMC];
__device__ __align__(256) __nv_bfloat16 g_w1c[(size_t)HID * 3 * DIMC];
__device__ __align__(256) __nv_bfloat16 g_w2c[(size_t)HID * 3 * DIMC];
__device__ __align__(256) __nv_bfloat16 g_w3c[(size_t)DIMC * 3 * HID];

// Attention operands (per (b,h) matrices)
// Qc/Kc: [B*H][SEQ][192] concat-split, rope applied, Q scaled by 1/8
__device__ __align__(256) __nv_bfloat16 g_qc[(size_t)BATCH * NH * SEQ * 192];
__device__ __align__(256) __nv_bfloat16 g_kc[(size_t)BATCH * NH * SEQ * 192];
// V transposed: [B*H][64][SEQ], hi and lo
__device__ __align__(256) __nv_bfloat16 g_vthi[(size_t)BATCH * NH * HD * SEQ];
__device__ __align__(256) __nv_bfloat16 g_vtlo[(size_t)BATCH * NH * HD * SEQ];

// ===========================================================================
// Helpers
// ===========================================================================
__device__ __forceinline__ unsigned smem_to_u32(const void* p) {
    unsigned a;
    asm("{ .reg .u64 t; cvta.to.shared.u64 t, %1; cvt.u32.u64 %0, t; }"
        : "=r"(a) : "l"(p));
    return a;
}
__device__ __forceinline__ void cp_async16(unsigned dst, const void* src) {
    asm volatile("cp.async.cg.shared.global [%0], [%1], 16;" :: "r"(dst), "l"(src));
}
__device__ __forceinline__ void cp_commit() {
    asm volatile("cp.async.commit_group;" ::: "memory");
}
template <int N>
__device__ __forceinline__ void cp_wait() {
    asm volatile("cp.async.wait_group %0;" :: "n"(N) : "memory");
}
__device__ __forceinline__ void ldm4(unsigned* r, unsigned addr) {
    asm volatile("ldmatrix.sync.aligned.m8n8.x4.shared.b16 {%0,%1,%2,%3}, [%4];"
        : "=r"(r[0]), "=r"(r[1]), "=r"(r[2]), "=r"(r[3]) : "r"(addr));
}
__device__ __forceinline__ void mma16816(float* d, const unsigned* a,
                                         unsigned b0, unsigned b1) {
    asm volatile(
        "mma.sync.aligned.m16n8k16.row.col.f32.bf16.bf16.f32 "
        "{%0,%1,%2,%3}, {%4,%5,%6,%7}, {%8,%9}, {%0,%1,%2,%3};"
        : "+f"(d[0]), "+f"(d[1]), "+f"(d[2]), "+f"(d[3])
        : "r"(a[0]), "r"(a[1]), "r"(a[2]), "r"(a[3]), "r"(b0), "r"(b1));
}
__device__ __forceinline__ unsigned pack_bf2(__nv_bfloat16 a, __nv_bfloat16 b) {
    unsigned short ua = *(unsigned short*)&a;
    unsigned short ub = *(unsigned short*)&b;
    return (unsigned)ua | ((unsigned)ub << 16);
}
__device__ __forceinline__ unsigned pack_hi2(float a, float b) {
    return pack_bf2(__float2bfloat16(a), __float2bfloat16(b));
}
__device__ __forceinline__ unsigned pack_lo2(float a, float b) {
    const __nv_bfloat16 ha = __float2bfloat16(a);
    const __nv_bfloat16 hb = __float2bfloat16(b);
    return pack_bf2(__float2bfloat16(a - __bfloat162float(ha)),
                    __float2bfloat16(b - __bfloat162float(hb)));
}
// swizzled smem byte offsets (rows of 384B / 128B, xor within 128B blocks)
__device__ __forceinline__ unsigned swz384(int row, int c) {   // c: 16B chunk 0..23
    return (unsigned)(row * 384 + ((c >> 3) << 7) + ((((c & 7) ^ (row & 7))) << 4));
}
__device__ __forceinline__ unsigned swz128(int row, int c) {   // c: 16B chunk 0..7
    return (unsigned)(row * 128 + (((c ^ (row & 7))) << 4));
}

// ===========================================================================
// Split kernels: fp32 -> K-concatenated bf16 hi/lo
//   A-type: [hi | lo | hi]     B-type: [hi | hi | lo]
// ===========================================================================
__global__ void split_a_kernel(const float* __restrict__ in,
                               __nv_bfloat16* __restrict__ out, int K, int n)
{
    const int i = blockIdx.x * blockDim.x + threadIdx.x;
    if (i < n) {
        const int r = i / K, k = i - r * K;
        const float v = in[i];
        const __nv_bfloat16 h = __float2bfloat16(v);
        const __nv_bfloat16 l = __float2bfloat16(v - __bfloat162float(h));
        __nv_bfloat16* o = out + (size_t)r * 3 * K + k;
        o[0] = h; o[K] = l; o[2 * K] = h;
    }
}
__global__ void split_b_kernel(const float* __restrict__ in,
                               __nv_bfloat16* __restrict__ out, int K, int n)
{
    const int i = blockIdx.x * blockDim.x + threadIdx.x;
    if (i < n) {
        const int r = i / K, k = i - r * K;
        const float v = in[i];
        const __nv_bfloat16 h = __float2bfloat16(v);
        const __nv_bfloat16 l = __float2bfloat16(v - __bfloat162float(h));
        __nv_bfloat16* o = out + (size_t)r * 3 * K + k;
        o[0] = h; o[K] = h; o[2 * K] = l;
    }
}

// ===========================================================================
// bf16 tensor-core NT GEMM via mma.sync (proven in R5)
// ===========================================================================
#define BM 128
#define BN 128
#define BK 64
#define STAGES 4
#define A_BYTES (BM * BK * 2)
#define B_BYTES (BN * BK * 2)
#define STG_BYTES (A_BYTES + B_BYTES)
#define GSMEM_SZ (STAGES * STG_BYTES)   // 128 KB

__global__ __launch_bounds__(256, 1) void gemm_mma_kernel(
    const __nv_bfloat16* __restrict__ A, const __nv_bfloat16* __restrict__ B,
    const float* __restrict__ bias,
    float* __restrict__ outf, __nv_bfloat16* __restrict__ outc,
    int N, int K)
{
    extern __shared__ char sm[];
    const unsigned sbase = smem_to_u32(sm);
    const int tid = threadIdx.x;
    const int wid = tid >> 5;
    const int lane = tid & 31;
    const int m0 = blockIdx.y * BM;
    const int n0 = blockIdx.x * BN;
    const int mw = (wid & 1) * 64;
    const int nw = (wid >> 1) * 32;

    float acc[4][4][4];
#pragma unroll
    for (int a = 0; a < 4; a++)
#pragma unroll
        for (int b = 0; b < 4; b++)
#pragma unroll
            for (int c = 0; c < 4; c++) acc[a][b][c] = 0.0f;

#define LOAD_STAGE(st, k0)                                                      \
    do {                                                                        \
        const unsigned s_a = sbase + (unsigned)(st) * STG_BYTES;                \
        const unsigned s_b = s_a + A_BYTES;                                     \
        _Pragma("unroll")                                                       \
        for (int i = 0; i < 4; i++) {                                           \
            const int idx = tid + i * 256;                                      \
            const int row = idx >> 3, ch = idx & 7;                             \
            cp_async16(s_a + row * 128 + ((ch ^ (row & 7)) << 4),               \
                       A + (size_t)(m0 + row) * K + (k0) + ch * 8);             \
        }                                                                       \
        _Pragma("unroll")                                                       \
        for (int i = 0; i < 4; i++) {                                           \
            const int idx = tid + i * 256;                                      \
            const int row = idx >> 3, ch = idx & 7;                             \
            cp_async16(s_b + row * 128 + ((ch ^ (row & 7)) << 4),               \
                       B + (size_t)(n0 + row) * K + (k0) + ch * 8);             \
        }                                                                       \
    } while (0)

    const int NK = K / BK;
#pragma unroll
    for (int s = 0; s < STAGES - 1; s++) {
        LOAD_STAGE(s, s * BK);
        cp_commit();
    }

    for (int ks = 0; ks < NK; ks++) {
        cp_wait<STAGES - 2>();
        __syncthreads();

        const int ns = ks + STAGES - 1;
        if (ns < NK) { LOAD_STAGE(ns & (STAGES - 1), ns * BK); }
        cp_commit();

        const unsigned s_a = sbase + (unsigned)(ks & (STAGES - 1)) * STG_BYTES;
        const unsigned s_b = s_a + A_BYTES;

#pragma unroll
        for (int kk = 0; kk < 4; kk++) {
            unsigned a_r[4][4], b_r[2][4];
#pragma unroll
            for (int mt = 0; mt < 4; mt++) {
                const int r = mw + mt * 16 + (lane & 15);
                const int cch = kk * 2 + (lane >> 4);
                ldm4(a_r[mt], s_a + r * 128 + ((cch ^ (r & 7)) << 4));
            }
#pragma unroll
            for (int ng = 0; ng < 2; ng++) {
                const int r = nw + ng * 16 + (lane & 7) + ((lane >> 4) << 3);
                const int cch = kk * 2 + ((lane >> 3) & 1);
                ldm4(b_r[ng], s_b + r * 128 + ((cch ^ (r & 7)) << 4));
            }
#pragma unroll
            for (int mt = 0; mt < 4; mt++) {
#pragma unroll
                for (int nt = 0; nt < 4; nt++) {
                    mma16816(acc[mt][nt], a_r[mt],
                             b_r[nt >> 1][(nt & 1) * 2],
                             b_r[nt >> 1][(nt & 1) * 2 + 1]);
                }
            }
        }
    }
    cp_wait<0>();

#pragma unroll
    for (int mt = 0; mt < 4; mt++) {
#pragma unroll
        for (int nt = 0; nt < 4; nt++) {
            const int row0 = m0 + mw + mt * 16 + (lane >> 2);
            const int col  = n0 + nw + nt * 8 + (lane & 3) * 2;
            float bv0 = 0.0f, bv1 = 0.0f;
            if (bias != nullptr) { bv0 = bias[col]; bv1 = bias[col + 1]; }
#pragma unroll
            for (int h = 0; h < 2; h++) {
                const int row = row0 + h * 8;
                const float v0 = acc[mt][nt][h * 2 + 0] + bv0;
                const float v1 = acc[mt][nt][h * 2 + 1] + bv1;
                if (outf != nullptr) {
                    *(float2*)&outf[(size_t)row * N + col] = make_float2(v0, v1);
                }
                if (outc != nullptr) {
                    const size_t base = (size_t)row * 3 * N + col;
                    const unsigned hp = pack_hi2(v0, v1);
                    *(unsigned*)&outc[base]         = hp;
                    *(unsigned*)&outc[base + N]     = pack_lo2(v0, v1);
                    *(unsigned*)&outc[base + 2 * N] = hp;
                }
            }
        }
    }
#undef LOAD_STAGE
}

// ===========================================================================
// Prep: rope + scale + concat-split for Q,K  ([B*H][SEQ][192])
// ===========================================================================
__global__ void prep_qk_kernel(const float* __restrict__ qkv,
                               __nv_bfloat16* __restrict__ Qc,
                               __nv_bfloat16* __restrict__ Kc)
{
    const int idx = blockIdx.x * blockDim.x + threadIdx.x;   // 2^22
    const int j = idx & 31;
    const int hh = (idx >> 5) & 15;
    const int n = (idx >> 9) & 2047;
    const int b = idx >> 20;

    const float inv_freq = expf(-(float)j * (9.210340371976184f / 32.0f));
    float sn, cs;
    sincosf((float)n * inv_freq, &sn, &cs);

    const size_t base = ((size_t)(b * SEQ + n) * 3) * DIMC + hh * HD;
    const float q0 = qkv[base + j],        q1 = qkv[base + j + 32];
    const float k0 = qkv[base + DIMC + j], k1 = qkv[base + DIMC + j + 32];
    const float qr0 = (q0 * cs - q1 * sn) * 0.125f;   // fold softmax scale into Q
    const float qr1 = (q1 * cs + q0 * sn) * 0.125f;
    const float kr0 = k0 * cs - k1 * sn;
    const float kr1 = k1 * cs + k0 * sn;

    __nv_bfloat16* q = Qc + ((size_t)(b * NH + hh) * SEQ + n) * 192;
    __nv_bfloat16* k = Kc + ((size_t)(b * NH + hh) * SEQ + n) * 192;
    // A-type [hi | lo | hi] for Q
    {
        const __nv_bfloat16 h0 = __float2bfloat16(qr0);
        const __nv_bfloat16 h1 = __float2bfloat16(qr1);
        q[j]            = h0;
        q[j + 32]       = h1;
        q[j + 64]       = __float2bfloat16(qr0 - __bfloat162float(h0));
        q[j + 96]       = __float2bfloat16(qr1 - __bfloat162float(h1));
        q[j + 128]      = h0;
        q[j + 160]      = h1;
    }
    // B-type [hi | hi | lo] for K
    {
        const __nv_bfloat16 h0 = __float2bfloat16(kr0);
        const __nv_bfloat16 h1 = __float2bfloat16(kr1);
        k[j]            = h0;
        k[j + 32]       = h1;
        k[j + 64]       = h0;
        k[j + 96]       = h1;
        k[j + 128]      = __float2bfloat16(kr0 - __bfloat162float(h0));
        k[j + 160]      = __float2bfloat16(kr1 - __bfloat162float(h1));
    }
}

// ===========================================================================
// Prep: V transpose + split  ([B*H][64][SEQ] hi/lo)
// ===========================================================================
__global__ __launch_bounds__(256) void prep_v_kernel(
    const float* __restrict__ qkv,
    __nv_bfloat16* __restrict__ Vthi, __nv_bfloat16* __restrict__ Vtlo)
{
    __shared__ float ts[64][65];
    const int tid = threadIdx.x;
    const int tile = blockIdx.x;        // bh*32 + ntile
    const int bh = tile >> 5;
    const int k0 = (tile & 31) * 64;
    const int b = bh >> 4, hh = bh & 15;

    for (int i = tid; i < 4096; i += 256) {
        const int r = i >> 6, c = i & 63;
        ts[c][r] = qkv[((size_t)(b * SEQ + k0 + r) * 3 + 2) * DIMC + hh * HD + c];
    }
    __syncthreads();
    for (int i = tid; i < 4096; i += 256) {
        const int d = i >> 6, n = i & 63;
        const float v = ts[d][n];
        const __nv_bfloat16 h = __float2bfloat16(v);
        const size_t off = ((size_t)bh * HD + d) * SEQ + k0 + n;
        Vthi[off] = h;
        Vtlo[off] = __float2bfloat16(v - __bfloat162float(h));
    }
}

// ===========================================================================
// Tensor-core flash attention (non-causal), split-bf16, online softmax.
// Block: 128 q rows x 8 warps (256 thr); 64-key tiles; double-buffered smem.
//   S = Q'[128,192] @ K'[64,192]^T  (split via K-concat)
//   O += Phi@Vhi + Plo@Vhi + Phi@Vlo  (P from in-register C->A conversion)
// smem: Q 48KB + 2 stages x (K' 24KB + Vhi 8KB + Vlo 8KB) = 128KB
// ===========================================================================
#define AQ 128
#define AK 64
#define AKC 192
#define ANT (SEQ / AK)          // 32 key tiles
#define ASM_Q 0
#define ASM_STG 49152
#define ASTG_VH 24576
#define ASTG_VL 32768
#define ASTG_SZ 40960
#define ASM_TOTAL (ASM_STG + 2 * ASTG_SZ)   // 131072

__global__ __launch_bounds__(256, 1) void attn_mma_kernel(
    const __nv_bfloat16* __restrict__ Qc, const __nv_bfloat16* __restrict__ Kc,
    const __nv_bfloat16* __restrict__ Vthi, const __nv_bfloat16* __restrict__ Vtlo,
    __nv_bfloat16* __restrict__ outc)
{
    extern __shared__ char sm[];
    const unsigned sb = smem_to_u32(sm);
    const int tid = threadIdx.x, wid = tid >> 5, lane = tid & 31;
    const int n0 = blockIdx.x * AQ;
    const int bh = blockIdx.y;
    const int b = bh >> 4, hh = bh & 15;
    const size_t qkrow0 = (size_t)bh * SEQ;

#define A_LOADSTAGE(buf, k0)                                                  \
    do {                                                                      \
        const unsigned s_k = sb + ASM_STG + (unsigned)(buf) * ASTG_SZ;        \
        for (int i = tid; i < 1536; i += 256) {                               \
            const int row = i / 24, c = i - row * 24;                         \
            cp_async16(s_k + swz384(row, c),                                  \
                       Kc + ((qkrow0 + (k0) + row) * AKC + c * 8));           \
        }                                                                     \
        const unsigned s_vh = s_k + ASTG_VH, s_vl = s_k + ASTG_VL;            \
        for (int i = tid; i < 512; i += 256) {                                \
            const int row = i >> 3, c = i & 7;                                \
            const size_t vs = ((size_t)bh * HD + row) * SEQ + (k0) + c * 8;   \
            cp_async16(s_vh + swz128(row, c), Vthi + vs);                     \
            cp_async16(s_vl + swz128(row, c), Vtlo + vs);                     \
        }                                                                     \
    } while (0)

    // Q tile + stage 0 in group 0; stage 1 in group 1
    for (int i = tid; i < 3072; i += 256) {
        const int row = i / 24, c = i - row * 24;
        cp_async16(sb + ASM_Q + swz384(row, c),
                   Qc + ((qkrow0 + n0 + row) * AKC + c * 8));
    }
    A_LOADSTAGE(0, 0);
    cp_commit();
    A_LOADSTAGE(1, AK);
    cp_commit();

    float m0 = -1e30f, m1 = -1e30f, l0 = 0.0f, l1 = 0.0f;
    float o[8][4];
#pragma unroll
    for (int nt = 0; nt < 8; nt++)
#pragma unroll
        for (int c = 0; c < 4; c++) o[nt][c] = 0.0f;

    const int ar = wid * 16 + (lane & 15);           // A ldmatrix row
    const int brq = (lane & 7) + ((lane >> 4) << 3); // B ldmatrix row base
    const int bcq = (lane >> 3) & 1;                 // B chunk phase

    for (int t = 0; t < ANT; t++) {
        if (t < ANT - 1) cp_wait<1>(); else cp_wait<0>();
        __syncthreads();
        const unsigned s_k  = sb + ASM_STG + (unsigned)(t & 1) * ASTG_SZ;
        const unsigned s_vh = s_k + ASTG_VH, s_vl = s_k + ASTG_VL;
        const unsigned s_q  = sb + ASM_Q;

        // ---- S = Q' K'^T  (fp32 accum; split terms via k'=192 concat)
        float p[8][4];
#pragma unroll
        for (int nt = 0; nt < 8; nt++)
#pragma unroll
            for (int c = 0; c < 4; c++) p[nt][c] = 0.0f;

#pragma unroll
        for (int ks = 0; ks < 12; ks++) {
            unsigned a[4];
            ldm4(a, s_q + swz384(ar, ks * 2 + (lane >> 4)));
            unsigned bb[4][4];
#pragma unroll
            for (int ng = 0; ng < 4; ng++)
                ldm4(bb[ng], s_k + swz384(ng * 16 + brq, ks * 2 + bcq));
#pragma unroll
            for (int nt = 0; nt < 8; nt++)
                mma16816(p[nt], a, bb[nt >> 1][(nt & 1) * 2],
                         bb[nt >> 1][(nt & 1) * 2 + 1]);
        }

        // ---- online softmax (rows: g=lane>>2 and g+8; quad reduction)
        float t0 = -1e30f, t1 = -1e30f;
#pragma unroll
        for (int nt = 0; nt < 8; nt++) {
            t0 = fmaxf(t0, fmaxf(p[nt][0], p[nt][1]));
            t1 = fmaxf(t1, fmaxf(p[nt][2], p[nt][3]));
        }
        t0 = fmaxf(t0, __shfl_xor_sync(0xffffffffu, t0, 1));
        t0 = fmaxf(t0, __shfl_xor_sync(0xffffffffu, t0, 2));
        t1 = fmaxf(t1, __shfl_xor_sync(0xffffffffu, t1, 1));
        t1 = fmaxf(t1, __shfl_xor_sync(0xffffffffu, t1, 2));
        const float mn0 = fmaxf(m0, t0), mn1 = fmaxf(m1, t1);
        const float al0 = __expf(m0 - mn0), al1 = __expf(m1 - mn1);
        m0 = mn0; m1 = mn1;
        float s0 = 0.0f, s1 = 0.0f;
#pragma unroll
        for (int nt = 0; nt < 8; nt++) {
            p[nt][0] = __expf(p[nt][0] - mn0);
            p[nt][1] = __expf(p[nt][1] - mn0);
            p[nt][2] = __expf(p[nt][2] - mn1);
            p[nt][3] = __expf(p[nt][3] - mn1);
            s0 += p[nt][0] + p[nt][1];
            s1 += p[nt][2] + p[nt][3];
        }
        s0 += __shfl_xor_sync(0xffffffffu, s0, 1);
        s0 += __shfl_xor_sync(0xffffffffu, s0, 2);
        s1 += __shfl_xor_sync(0xffffffffu, s1, 1);
        s1 += __shfl_xor_sync(0xffffffffu, s1, 2);
        l0 = l0 * al0 + s0;
        l1 = l1 * al1 + s1;
#pragma unroll
        for (int nt = 0; nt < 8; nt++) {
            o[nt][0] *= al0; o[nt][1] *= al0;
            o[nt][2] *= al1; o[nt][3] *= al1;
        }

        // ---- O += P @ V  (C->A fragment conversion; 3 split terms)
#pragma unroll
        for (int kt = 0; kt < 4; kt++) {
            unsigned phi[4], plo[4];
            phi[0] = pack_hi2(p[2 * kt][0], p[2 * kt][1]);
            phi[1] = pack_hi2(p[2 * kt][2], p[2 * kt][3]);
            phi[2] = pack_hi2(p[2 * kt + 1][0], p[2 * kt + 1][1]);
            phi[3] = pack_hi2(p[2 * kt + 1][2], p[2 * kt + 1][3]);
            plo[0] = pack_lo2(p[2 * kt][0], p[2 * kt][1]);
            plo[1] = pack_lo2(p[2 * kt][2], p[2 * kt][3]);
            plo[2] = pack_lo2(p[2 * kt + 1][0], p[2 * kt + 1][1]);
            plo[3] = pack_lo2(p[2 * kt + 1][2], p[2 * kt + 1][3]);
#pragma unroll
            for (int ng = 0; ng < 4; ng++) {
                unsigned bhf[4], blf[4];
                ldm4(bhf, s_vh + swz128(ng * 16 + brq, kt * 2 + bcq));
                ldm4(blf, s_vl + swz128(ng * 16 + brq, kt * 2 + bcq));
                mma16816(o[2 * ng],     phi, bhf[0], bhf[1]);
                mma16816(o[2 * ng + 1], phi, bhf[2], bhf[3]);
                mma16816(o[2 * ng],     plo, bhf[0], bhf[1]);
                mma16816(o[2 * ng + 1], plo, bhf[2], bhf[3]);
                mma16816(o[2 * ng],     phi, blf[0], blf[1]);
                mma16816(o[2 * ng + 1], phi, blf[2], blf[3]);
            }
        }

        __syncthreads();
        if (t + 2 < ANT) {
            A_LOADSTAGE((t & 1), (t + 2) * AK);
            cp_commit();
        }
    }

    // ---- epilogue: normalize, write A-type concat split [hi|lo|hi]
    const float il0 = 1.0f / l0, il1 = 1.0f / l1;
    const int g = lane >> 2;
    const int row0 = n0 + wid * 16 + g;
    const int row1 = row0 + 8;
#pragma unroll
    for (int nt = 0; nt < 8; nt++) {
        const int d = nt * 8 + (lane & 3) * 2;
        const float x0 = o[nt][0] * il0, x1 = o[nt][1] * il0;
        const float y0 = o[nt][2] * il1, y1 = o[nt][3] * il1;
        const size_t b0 = (size_t)(b * SEQ + row0) * (3 * DIMC) + hh * HD + d;
        const size_t b1 = (size_t)(b * SEQ + row1) * (3 * DIMC) + hh * HD + d;
        const unsigned hx = pack_hi2(x0, x1);
        const unsigned hy = pack_hi2(y0, y1);
        *(unsigned*)&outc[b0]            = hx;
        *(unsigned*)&outc[b0 + DIMC]     = pack_lo2(x0, x1);
        *(unsigned*)&outc[b0 + 2 * DIMC] = hx;
        *(unsigned*)&outc[b1]            = hy;
        *(unsigned*)&outc[b1 + DIMC]     = pack_lo2(y0, y1);
        *(unsigned*)&outc[b1 + 2 * DIMC] = hy;
    }
#undef A_LOADSTAGE
}

// ===========================================================================
// SwiGLU elementwise -> concat split bf16 (segments of HID)
// ===========================================================================
__global__ void silu_split_kernel(const float* __restrict__ x1,
                                  const float* __restrict__ x2,
                                  __nv_bfloat16* __restrict__ outc, int n)
{
    const int i = blockIdx.x * blockDim.x + threadIdx.x;
    if (i < n) {
        const int r = i / HID, k = i - r * HID;
        const float a = x1[i];
        const float v = (a / (1.0f + expf(-a))) * x2[i];
        const __nv_bfloat16 h = __float2bfloat16(v);
        const __nv_bfloat16 l = __float2bfloat16(v - __bfloat162float(h));
        __nv_bfloat16* o = outc + (size_t)r * 3 * HID + k;
        o[0] = h; o[HID] = l; o[2 * HID] = h;
    }
}

// ===========================================================================
// kernel_launch
// ===========================================================================
extern "C" void kernel_launch(void* const* d_in, const int* in_sizes, int n_in,
                              void* d_out, int out_size)
{
    const float* x      = (const float*)d_in[0];
    const float* qkv_w  = (const float*)d_in[1];
    const float* proj_w = (const float*)d_in[2];
    const float* proj_b = (const float*)d_in[3];
    const float* w1_w   = (const float*)d_in[4];
    const float* w1_b   = (const float*)d_in[5];
    const float* w2_w   = (const float*)d_in[6];
    const float* w2_b   = (const float*)d_in[7];
    const float* w3_w   = (const float*)d_in[8];
    const float* w3_b   = (const float*)d_in[9];
    float* out = (float*)d_out;

    cudaFuncSetAttribute(gemm_mma_kernel,
                         cudaFuncAttributeMaxDynamicSharedMemorySize, GSMEM_SZ);
    cudaFuncSetAttribute(attn_mma_kernel,
                         cudaFuncAttributeMaxDynamicSharedMemorySize, ASM_TOTAL);

    float *qkv, *x1, *x2;
    cudaGetSymbolAddress((void**)&qkv, g_qkv);
    cudaGetSymbolAddress((void**)&x1,  g_x1);
    cudaGetSymbolAddress((void**)&x2,  g_x2);
    __nv_bfloat16 *xc, *attnc, *projc, *hc, *wqkvc, *wprojc, *w1c, *w2c, *w3c;
    __nv_bfloat16 *qc, *kc, *vthi, *vtlo;
    cudaGetSymbolAddress((void**)&xc,    g_xc);
    cudaGetSymbolAddress((void**)&attnc, g_attnc);
    cudaGetSymbolAddress((void**)&projc, g_projc);
    cudaGetSymbolAddress((void**)&hc,    g_hc);
    cudaGetSymbolAddress((void**)&wqkvc, g_wqkvc);
    cudaGetSymbolAddress((void**)&wprojc,g_wprojc);
    cudaGetSymbolAddress((void**)&w1c,   g_w1c);
    cudaGetSymbolAddress((void**)&w2c,   g_w2c);
    cudaGetSymbolAddress((void**)&w3c,   g_w3c);
    cudaGetSymbolAddress((void**)&qc,    g_qc);
    cudaGetSymbolAddress((void**)&kc,    g_kc);
    cudaGetSymbolAddress((void**)&vthi,  g_vthi);
    cudaGetSymbolAddress((void**)&vtlo,  g_vtlo);

    // Splits (x is A-type; weights are B-type)
    split_a_kernel<<<(MTOK * DIMC) / 256, 256>>>(x, xc, DIMC, MTOK * DIMC);
    split_b_kernel<<<(3 * DIMC * DIMC) / 256, 256>>>(qkv_w, wqkvc, DIMC, 3 * DIMC * DIMC);
    split_b_kernel<<<(DIMC * DIMC) / 256, 256>>>(proj_w, wprojc, DIMC, DIMC * DIMC);
    split_b_kernel<<<(HID * DIMC) / 256, 256>>>(w1_w, w1c, DIMC, HID * DIMC);
    split_b_kernel<<<(HID * DIMC) / 256, 256>>>(w2_w, w2c, DIMC, HID * DIMC);
    split_b_kernel<<<(DIMC * HID) / 256, 256>>>(w3_w, w3c, HID, DIMC * HID);

    // 1) QKV projection -> fp32
    gemm_mma_kernel<<<dim3(3 * DIMC / BN, MTOK / BM), 256, GSMEM_SZ>>>(
        xc, wqkvc, nullptr, qkv, nullptr, 3 * DIMC, 3 * DIMC);

    // 2) Rope + split prep for attention operands
    prep_qk_kernel<<<(BATCH * SEQ * NH * 32) / 256, 256>>>(qkv, qc, kc);
    prep_v_kernel<<<BATCH * NH * (SEQ / 64), 256>>>(qkv, vthi, vtlo);

    // 3) Tensor-core attention -> concat split bf16
    attn_mma_kernel<<<dim3(SEQ / AQ, BATCH * NH), 256, ASM_TOTAL>>>(
        qc, kc, vthi, vtlo, attnc);

    // 4) Output projection (+bias) -> concat split bf16
    gemm_mma_kernel<<<dim3(DIMC / BN, MTOK / BM), 256, GSMEM_SZ>>>(
        attnc, wprojc, proj_b, nullptr, projc, DIMC, 3 * DIMC);

    // 5) MLP up projections -> fp32
    gemm_mma_kernel<<<dim3(HID / BN, MTOK / BM), 256, GSMEM_SZ>>>(
        projc, w1c, w1_b, x1, nullptr, HID, 3 * DIMC);
    gemm_mma_kernel<<<dim3(HID / BN, MTOK / BM), 256, GSMEM_SZ>>>(
        projc, w2c, w2_b, x2, nullptr, HID, 3 * DIMC);

    // 6) SwiGLU -> concat split bf16
    silu_split_kernel<<<(MTOK * HID) / 256, 256>>>(x1, x2, hc, MTOK * HID);

    // 7) Down projection -> fp32 out
    gemm_mma_kernel<<<dim3(DIMC / BN, MTOK / BM), 256, GSMEM_SZ>>>(
        hc, w3c, w3_b, out, nullptr, DIMC, 3 * HID);
}